// round 15
// baseline (speedup 1.0000x reference)
#include <cuda_runtime.h>
#include <cuda_bf16.h>

#define EPSF 1e-5f
typedef unsigned short u16;
typedef unsigned int u32;
typedef unsigned long long u64;

// ---------------- device scratch ----------------
static __device__ __align__(256) float g_xs  [6291456];   // LIF1 spikes f32 [img][c][hw]
static __device__ __align__(256) u16   g_xsb [6291456];   // conv B bf16 im2col [img][p][k]
static __device__ __align__(256) float g_y   [3145728];   // conv+BN y1 rows [img][768][256]
static __device__ __align__(256) float g_y2T [1572864];   // y2 BN'd transposed [img][h][n=256][d=32]
static __device__ __align__(256) float g_yp  [3][3145728];// conv K-split partials
static __device__ __align__(256) u16   g_sp3b[6291456];   // LIF3 spikes bf16 [img][c][hw]
static __device__ __align__(256) u16   g_sp3T[6291456];   // transposed [img][hw][c]
static __device__ __align__(256) u16   g_wc3 [3538944];   // Wconv 3-term bf16 [3][768][1536]
static __device__ __align__(256) u16   g_wp3 [442368];    // Wproj 3-term bf16 [3][384][384]

// ---------------- fp32x2 helpers ----------------
__device__ __forceinline__ u64 pk2(float lo, float hi) {
    u64 r; asm("mov.b64 %0, {%1,%2};" : "=l"(r) : "f"(lo), "f"(hi)); return r;
}
__device__ __forceinline__ void upk2(u64 v, float& lo, float& hi) {
    asm("mov.b64 {%0,%1}, %2;" : "=f"(lo), "=f"(hi) : "l"(v));
}
__device__ __forceinline__ u64 ffma2(u64 a, u64 b, u64 c) {
    u64 d; asm("fma.rn.f32x2 %0, %1, %2, %3;" : "=l"(d) : "l"(a), "l"(b), "l"(c)); return d;
}

// ---------------- mma / ldmatrix / cp.async helpers ----------------
__device__ __forceinline__ void mma16816(
    float& c0, float& c1, float& c2, float& c3,
    u32 a0, u32 a1, u32 a2, u32 a3, u32 b0, u32 b1)
{
    asm volatile(
        "mma.sync.aligned.m16n8k16.row.col.f32.bf16.bf16.f32 "
        "{%0,%1,%2,%3}, {%4,%5,%6,%7}, {%8,%9}, {%0,%1,%2,%3};"
        : "+f"(c0), "+f"(c1), "+f"(c2), "+f"(c3)
        : "r"(a0), "r"(a1), "r"(a2), "r"(a3), "r"(b0), "r"(b1));
}
__device__ __forceinline__ void ldm_x4(u32& r0, u32& r1, u32& r2, u32& r3, u32 addr) {
    asm volatile("ldmatrix.sync.aligned.m8n8.x4.shared.b16 {%0,%1,%2,%3}, [%4];"
                 : "=r"(r0), "=r"(r1), "=r"(r2), "=r"(r3) : "r"(addr));
}
__device__ __forceinline__ void cp16(u32 saddr, const void* g) {
    asm volatile("cp.async.cg.shared.global [%0], [%1], 16;" :: "r"(saddr), "l"(g));
}
#define CP_COMMIT() asm volatile("cp.async.commit_group;" ::: "memory")
#define CP_WAIT1()  asm volatile("cp.async.wait_group 1;" ::: "memory")
#define CP_WAIT0()  asm volatile("cp.async.wait_group 0;" ::: "memory")
__device__ __forceinline__ u32 smem_u32(const void* p) {
    u32 a;
    asm("{ .reg .u64 t; cvta.to.shared.u64 t, %1; cvt.u32.u64 %0, t; }" : "=r"(a) : "l"(p));
    return a;
}
__device__ __forceinline__ void split3(float w, u16& h0, u16& m0, u16& l0) {
    __nv_bfloat16 hh = __float2bfloat16(w);
    float r1 = w - __bfloat162float(hh);
    __nv_bfloat16 mm = __float2bfloat16(r1);
    float r2 = r1 - __bfloat162float(mm);
    h0 = __bfloat16_as_ushort(hh);
    m0 = __bfloat16_as_ushort(mm);
    l0 = __bfloat16_as_ushort(__float2bfloat16(r2));
}

// ============================================================
// Kernel A: LIF over T on x -> spikes g_xs (f32)
// ============================================================
__global__ void __launch_bounds__(256) lif1_kernel(const float* __restrict__ x) {
    const int S = 4 * 384 * 1024;
    int i = blockIdx.x * blockDim.x + threadIdx.x;
    float v = 0.0f;
#pragma unroll
    for (int t = 0; t < 4; t++) {
        v = 0.5f * (v + x[(size_t)t * S + i]);
        bool s = (v >= 1.0f);
        g_xs[(size_t)t * S + i] = s ? 1.0f : 0.0f;
        v = s ? 0.0f : v;
    }
}

// ============================================================
// Kernel A2: im2col bf16 for conv B
// ============================================================
__global__ void __launch_bounds__(256) im2col_kernel() {
    int idx = blockIdx.x * 256 + threadIdx.x;
    int img = idx / 98304;
    int r = idx - img * 98304;
    int c = r >> 8;
    int pp = r & 255;
    int ii = pp >> 4, jj = pp & 15;
    const float* base = g_xs + (size_t)img * 393216 + c * 1024;
    float2 a = *(const float2*)&base[(2 * ii) * 32 + 2 * jj];
    float2 b = *(const float2*)&base[(2 * ii + 1) * 32 + 2 * jj];
    ushort4 o;
    o.x = (a.x > 0.5f) ? 0x3F80 : 0;
    o.y = (a.y > 0.5f) ? 0x3F80 : 0;
    o.z = (b.x > 0.5f) ? 0x3F80 : 0;
    o.w = (b.y > 0.5f) ? 0x3F80 : 0;
    *(ushort4*)&g_xsb[((size_t)img * 256 + pp) * 1536 + c * 4] = o;
}

// ============================================================
// Kernel W: split fp32 weights into 3 bf16 terms (Dekker, exact)
// ============================================================
__global__ void __launch_bounds__(256) wsplit_kernel(
    const float* __restrict__ Wc, const float* __restrict__ Wp)
{
    int i = blockIdx.x * 256 + threadIdx.x;
    float w;
    u16* d;
    int n, off;
    if (i < 1179648) { off = i; w = Wc[off]; d = g_wc3; n = 1179648; }
    else             { off = i - 1179648; w = Wp[off]; d = g_wp3; n = 147456; }
    u16 h0, m0, l0;
    split3(w, h0, m0, l0);
    d[off]         = h0;
    d[n + off]     = m0;
    d[2 * n + off] = l0;
}

// ============================================================
// Kernel B: conv as mma.sync GEMM, K-split 3 -> fp32 partials.
// (unchanged from R12 measured 84.3us)
// ============================================================
__global__ void __launch_bounds__(256) conv_mma_kernel()
{
    extern __shared__ u32 smu[];
    const u32 sbase = smem_u32(smu);
    const int tid = threadIdx.x;
    const int wid = tid >> 5, lane = tid & 31;
    const int g = lane >> 2, t = lane & 3;
    const int wm = wid >> 1, wn = wid & 1;
    const int bx = blockIdx.x;
    const int ks = bx / 192;
    const int rem = bx % 192;
    const int img = rem / 12;
    const int r12 = rem % 12;
    const int ot = r12 >> 1, pt = r12 & 1;
    const int obase = ot * 128, pbase = pt * 128;
    const int kbase = ks * 512;
    const u16* Asrc = g_wc3;
    const u16* Bsrc = g_xsb + ((size_t)img * 256 + pbase) * 1536;

    float acc[2][8][4];
#pragma unroll
    for (int mt = 0; mt < 2; mt++)
#pragma unroll
        for (int nt = 0; nt < 8; nt++)
#pragma unroll
            for (int q = 0; q < 4; q++) acc[mt][nt][q] = 0.0f;

    auto ldChunk = [&](int c, int buf) {
        u32 sb = sbase + buf * 40960;
        int k0 = kbase + c * 32;
#pragma unroll
        for (int it = 0; it < 6; it++) {
            int e = tid + 256 * it;
            int j = e >> 9;
            int r = (e >> 2) & 127;
            int kg = e & 3;
            cp16(sb + (j * 2560 + r * 20 + kg * 4) * 4,
                 &Asrc[(size_t)j * 1179648 + (size_t)(obase + r) * 1536 + k0 + kg * 8]);
        }
#pragma unroll
        for (int it = 0; it < 2; it++) {
            int e = tid + 256 * it;
            int r = e >> 2, kg = e & 3;
            cp16(sb + (7680 + r * 20 + kg * 4) * 4,
                 &Bsrc[(size_t)r * 1536 + k0 + kg * 8]);
        }
        CP_COMMIT();
    };

    const int aRow = wm * 32 + (lane & 15);
    const int aColw = ((lane >> 4) & 1) * 4;
    const int bRowB = wn * 64 + ((lane >> 4) & 1) * 8 + (lane & 7);
    const int bColw = ((lane >> 3) & 1) * 4;

    ldChunk(0, 0);
    for (int c = 0; c < 16; c++) {
        int buf = c & 1;
        if (c + 1 < 16) { ldChunk(c + 1, buf ^ 1); CP_WAIT1(); }
        else            { CP_WAIT0(); }
        __syncthreads();
        u32 soff = sbase + buf * 40960;
#pragma unroll
        for (int k16 = 0; k16 < 2; k16++) {
            u32 bfr[8][2];
#pragma unroll
            for (int p = 0; p < 4; p++) {
                u32 addr = soff + ((7680 + (bRowB + p * 16) * 20 + k16 * 8 + bColw) << 2);
                ldm_x4(bfr[2 * p][0], bfr[2 * p][1],
                       bfr[2 * p + 1][0], bfr[2 * p + 1][1], addr);
            }
#pragma unroll
            for (int j = 0; j < 3; j++) {
#pragma unroll
                for (int mt = 0; mt < 2; mt++) {
                    u32 addr = soff + ((j * 2560 + (aRow + mt * 16) * 20 + k16 * 8 + aColw) << 2);
                    u32 a0, a1, a2, a3;
                    ldm_x4(a0, a1, a2, a3, addr);
#pragma unroll
                    for (int nt = 0; nt < 8; nt++)
                        mma16816(acc[mt][nt][0], acc[mt][nt][1],
                                 acc[mt][nt][2], acc[mt][nt][3],
                                 a0, a1, a2, a3, bfr[nt][0], bfr[nt][1]);
                }
            }
        }
        __syncthreads();
    }

    float* yo = g_yp[ks];
#pragma unroll
    for (int mt = 0; mt < 2; mt++) {
        int o0 = obase + wm * 32 + mt * 16 + g;
        int o1 = o0 + 8;
#pragma unroll
        for (int nt = 0; nt < 8; nt++) {
            int p = pbase + wn * 64 + nt * 8 + 2 * t;
            *(float2*)&yo[((size_t)img * 768 + o0) * 256 + p] =
                make_float2(acc[mt][nt][0], acc[mt][nt][1]);
            *(float2*)&yo[((size_t)img * 768 + o1) * 256 + p] =
                make_float2(acc[mt][nt][2], acc[mt][nt][3]);
        }
    }
}

// ============================================================
// Kernel B2: reduce partials + BN1.
// y1 rows -> g_y (layout unchanged); y2 rows -> g_y2T transposed.
// grid 192 (img*12+h), 256 thr.
// ============================================================
__global__ void __launch_bounds__(256) reduce_split_kernel(
    const float* __restrict__ g1, const float* __restrict__ b1)
{
    __shared__ float ts[32 * 260];
    const int bx = blockIdx.x;
    const int img = bx / 12;
    const int h = bx % 12;
    const int tid = threadIdx.x;
    const float rs = rsqrtf(1.0f + EPSF);

    // Phase A: y1 rows (o = h*64 + 0..31) -> g_y (same layout)
#pragma unroll
    for (int it = 0; it < 8; it++) {
        int e = it * 256 + tid;
        int dd = e >> 6, n4 = (e & 63) * 4;
        int o = h * 64 + dd;
        size_t idx = ((size_t)img * 768 + o) * 256 + n4;
        float4 a = *(const float4*)&g_yp[0][idx];
        float4 b = *(const float4*)&g_yp[1][idx];
        float4 c = *(const float4*)&g_yp[2][idx];
        float bn = g1[o] * rs, bt = b1[o];
        *(float4*)&g_y[idx] = make_float4(
            (a.x + b.x + c.x) * bn + bt, (a.y + b.y + c.y) * bn + bt,
            (a.z + b.z + c.z) * bn + bt, (a.w + b.w + c.w) * bn + bt);
    }
    // Phase B: y2 rows (o = h*64 + 32 + dd) -> smem tile -> g_y2T [n][d]
#pragma unroll
    for (int it = 0; it < 8; it++) {
        int e = it * 256 + tid;
        int dd = e >> 6, n4 = (e & 63) * 4;
        int o = h * 64 + 32 + dd;
        size_t idx = ((size_t)img * 768 + o) * 256 + n4;
        float4 a = *(const float4*)&g_yp[0][idx];
        float4 b = *(const float4*)&g_yp[1][idx];
        float4 c = *(const float4*)&g_yp[2][idx];
        float bn = g1[o] * rs, bt = b1[o];
        *(float4*)&ts[dd * 260 + n4] = make_float4(
            (a.x + b.x + c.x) * bn + bt, (a.y + b.y + c.y) * bn + bt,
            (a.z + b.z + c.z) * bn + bt, (a.w + b.w + c.w) * bn + bt);
    }
    __syncthreads();
    // write transposed: thread tid owns column n=tid
    {
        float col[32];
#pragma unroll
        for (int d = 0; d < 32; d++) col[d] = ts[d * 260 + tid];
        float* dst = &g_y2T[(((size_t)img * 12 + h) * 256 + tid) * 32];
#pragma unroll
        for (int q = 0; q < 8; q++)
            *(float4*)&dst[q * 4] = make_float4(col[4 * q], col[4 * q + 1],
                                                col[4 * q + 2], col[4 * q + 3]);
    }
}

// ============================================================
// Kernel C: fused attn GEMM -> LIF2 -> out GEMM(ksplit8) -> LIF3
// y2 transposed [n][d] -> GEMM2 fragment loads hit 1 line.
// smem (floats): y1s[32][256]@0 | xr[2][32][32]@8192 |
//   y2T[256][36]@10240 | ss/sp[9216]@19456  -> 114,688 B
// ============================================================
__global__ void __launch_bounds__(256, 2) attn_fused_kernel(
    const float* __restrict__ frx, const float* __restrict__ fra)
{
    extern __shared__ __align__(16) float sm[];
    float* y1s = sm;
    float* y2T = sm + 10240;
    float* ss  = sm + 19456;
    float* sp  = sm + 19456;   // overlay on ss (post-GEMM2)
    const u32 sbase = smem_u32(sm);

    const int bx = blockIdx.x;
    const int mt = bx & 31;
    const int h  = (bx >> 5) % 12;
    const int b  = bx / 384;
    const int tid = threadIdx.x;

    const int ng = tid >> 2;
    const int mg = tid & 3;
    const int n0 = ng * 4, m0 = mg * 8;
    const int kg = tid >> 5;
    const int lane = tid & 31;
    const int dg = lane >> 2;          // GEMM2 d-tile = 4*dg .. 4*dg+3
    const int mq = lane & 3;
    const int rd = tid >> 3;
    const int rm = (tid & 7) * 4;

    const float scale1 = rsqrtf(frx[h] * 32.0f);
    const float scale2 = rsqrtf(fra[h] * 256.0f);

    float v2[4][8];
    float v3[4];
#pragma unroll
    for (int i = 0; i < 4; i++)
#pragma unroll
        for (int j = 0; j < 8; j++) v2[i][j] = 0.0f;
#pragma unroll
    for (int i = 0; i < 4; i++) v3[i] = 0.0f;

    auto issue_y1 = [&](int img) {
        const float* ybase = g_y + ((size_t)img * 768 + h * 64) * 256;
#pragma unroll
        for (int r = 0; r < 8; r++) {
            int e = tid + 256 * r;
            int d = e >> 6, c4 = (e & 63) * 4;
            cp16(sbase + (u32)(d * 256 + c4) * 4, &ybase[d * 256 + c4]);
        }
        CP_COMMIT();
    };
    auto issue_y2 = [&](int img) {
        const float* ybase = g_y2T + (((size_t)img * 12 + h) * 256) * 32;
#pragma unroll
        for (int r = 0; r < 8; r++) {
            int e = tid + 256 * r;
            int rr = e >> 3, ch = (e & 7) * 4;
            cp16(sbase + (u32)(10240 + rr * 36 + ch) * 4, &ybase[rr * 32 + ch]);
        }
        CP_COMMIT();
    };
    auto load_xr = [&](int img, int buf) {
        const float* xbase = g_xs + ((size_t)img * 384 + h * 32) * 1024 + mt * 32;
        int d = tid >> 3, c4 = (tid & 7) * 4;
        float4 v = *(const float4*)&xbase[d * 1024 + c4];
        float* dst = sm + 8192 + buf * 1024;
        *(float4*)&dst[d * 32 + c4] = make_float4(
            v.x * scale1, v.y * scale1, v.z * scale1, v.w * scale1);
    };

    issue_y1(b);
    issue_y2(b);
    load_xr(b, 0);

    for (int t = 0; t < 4; t++) {
        const int img = t * 4 + b;
        CP_WAIT0();
        __syncthreads();
        if (t < 3) load_xr(img + 4, (t + 1) & 1);
        const float* xrs = sm + 8192 + (t & 1) * 1024;

        // GEMM1
        u64 acc[4][4];
#pragma unroll
        for (int i = 0; i < 4; i++)
#pragma unroll
            for (int q = 0; q < 4; q++) acc[i][q] = pk2(v2[i][2 * q], v2[i][2 * q + 1]);
#pragma unroll 8
        for (int d = 0; d < 32; d++) {
            float4 a4 = *(const float4*)&y1s[d * 256 + n0];
            ulonglong2 x0 = *(const ulonglong2*)&xrs[d * 32 + m0];
            ulonglong2 x1 = *(const ulonglong2*)&xrs[d * 32 + m0 + 4];
            float av[4] = {a4.x, a4.y, a4.z, a4.w};
#pragma unroll
            for (int i = 0; i < 4; i++) {
                u64 ar = pk2(av[i], av[i]);
                acc[i][0] = ffma2(ar, x0.x, acc[i][0]);
                acc[i][1] = ffma2(ar, x0.y, acc[i][1]);
                acc[i][2] = ffma2(ar, x1.x, acc[i][2]);
                acc[i][3] = ffma2(ar, x1.y, acc[i][3]);
            }
        }
        // LIF2 (spikes stored as scale2 / 0; bit-exact commuted product)
#pragma unroll
        for (int i = 0; i < 4; i++) {
            float s[8];
#pragma unroll
            for (int q = 0; q < 4; q++) {
                float lo, hi;
                upk2(acc[i][q], lo, hi);
                lo *= 0.5f; hi *= 0.5f;
                s[2 * q]     = (lo >= 1.0f) ? scale2 : 0.0f;
                s[2 * q + 1] = (hi >= 1.0f) ? scale2 : 0.0f;
                v2[i][2 * q]     = (lo >= 1.0f) ? 0.0f : lo;
                v2[i][2 * q + 1] = (hi >= 1.0f) ? 0.0f : hi;
            }
            *(float4*)&ss[(n0 + i) * 36 + m0]     = make_float4(s[0], s[1], s[2], s[3]);
            *(float4*)&ss[(n0 + i) * 36 + m0 + 4] = make_float4(s[4], s[5], s[6], s[7]);
        }
        __syncthreads();
        if (t < 3) issue_y1(img + 4);

        // GEMM2 (ksplit 8): thread tile d = 4*dg..+3, m = mq*8..+7
        u64 acc2[4][4];
#pragma unroll
        for (int i = 0; i < 4; i++)
#pragma unroll
            for (int q = 0; q < 4; q++) acc2[i][q] = 0ull;
#pragma unroll
        for (int nn = 0; nn < 32; nn += 4) {
            int n = kg * 32 + nn;
            float4 yv0 = *(const float4*)&y2T[(n + 0) * 36 + dg * 4];
            float4 yv1 = *(const float4*)&y2T[(n + 1) * 36 + dg * 4];
            float4 yv2 = *(const float4*)&y2T[(n + 2) * 36 + dg * 4];
            float4 yv3 = *(const float4*)&y2T[(n + 3) * 36 + dg * 4];
            float bv[4][4] = {{yv0.x, yv0.y, yv0.z, yv0.w}, {yv1.x, yv1.y, yv1.z, yv1.w},
                              {yv2.x, yv2.y, yv2.z, yv2.w}, {yv3.x, yv3.y, yv3.z, yv3.w}};
#pragma unroll
            for (int j = 0; j < 4; j++) {
                ulonglong2 s0 = *(const ulonglong2*)&ss[(n + j) * 36 + mq * 8];
                ulonglong2 s1 = *(const ulonglong2*)&ss[(n + j) * 36 + mq * 8 + 4];
#pragma unroll
                for (int i = 0; i < 4; i++) {
                    u64 ar = pk2(bv[j][i], bv[j][i]);
                    acc2[i][0] = ffma2(ar, s0.x, acc2[i][0]);
                    acc2[i][1] = ffma2(ar, s0.y, acc2[i][1]);
                    acc2[i][2] = ffma2(ar, s1.x, acc2[i][2]);
                    acc2[i][3] = ffma2(ar, s1.y, acc2[i][3]);
                }
            }
        }
        __syncthreads();
        if (t < 3) issue_y2(img + 4);
#pragma unroll
        for (int i = 0; i < 4; i++) {
            float* dst = &sp[kg * 1152 + (4 * dg + i) * 36 + mq * 8];
            *(ulonglong2*)dst       = make_ulonglong2(acc2[i][0], acc2[i][1]);
            *(ulonglong2*)(dst + 4) = make_ulonglong2(acc2[i][2], acc2[i][3]);
        }
        __syncthreads();

        // reduce + LIF3 + bf16 spike store
        float4 sum = make_float4(v3[0], v3[1], v3[2], v3[3]);
#pragma unroll
        for (int k = 0; k < 8; k++) {
            float4 p = *(const float4*)&sp[k * 1152 + rd * 36 + rm];
            sum.x += p.x; sum.y += p.y; sum.z += p.z; sum.w += p.w;
        }
        sum.x *= 0.5f; sum.y *= 0.5f; sum.z *= 0.5f; sum.w *= 0.5f;
        ushort4 sb;
        sb.x = (sum.x >= 1.0f) ? 0x3F80 : 0; v3[0] = (sum.x >= 1.0f) ? 0.0f : sum.x;
        sb.y = (sum.y >= 1.0f) ? 0x3F80 : 0; v3[1] = (sum.y >= 1.0f) ? 0.0f : sum.y;
        sb.z = (sum.z >= 1.0f) ? 0x3F80 : 0; v3[2] = (sum.z >= 1.0f) ? 0.0f : sum.z;
        sb.w = (sum.w >= 1.0f) ? 0x3F80 : 0; v3[3] = (sum.w >= 1.0f) ? 0.0f : sum.w;
        *(ushort4*)&g_sp3b[((size_t)img * 384 + h * 32 + rd) * 1024 + mt * 32 + rm] = sb;
        __syncthreads();
    }
}

// ============================================================
// Kernel T: transpose bf16 spikes [c][hw] -> [hw][c] per img
// ============================================================
__global__ void __launch_bounds__(256) transpose_sp3_kernel() {
    __shared__ u16 ts[64][72];
    int bx = blockIdx.x;
    int img = bx / 96;
    int r = bx % 96;
    int c0 = (r / 16) * 64;
    int hw0 = (r % 16) * 64;
    int tid = threadIdx.x;
#pragma unroll
    for (int it = 0; it < 4; it++) {
        int e = tid + 256 * it;
        int row = e >> 4, q = e & 15;
        u64 v = *(const u64*)&g_sp3b[((size_t)img * 384 + c0 + row) * 1024 + hw0 + q * 4];
        *(u64*)&ts[row][q * 4] = v;
    }
    __syncthreads();
#pragma unroll
    for (int it = 0; it < 4; it++) {
        int e = tid + 256 * it;
        int orow = e >> 4, q = e & 15;
        u64 v = (u64)ts[q * 4 + 0][orow]
              | ((u64)ts[q * 4 + 1][orow] << 16)
              | ((u64)ts[q * 4 + 2][orow] << 32)
              | ((u64)ts[q * 4 + 3][orow] << 48);
        *(u64*)&g_sp3T[((size_t)img * 1024 + hw0 + orow) * 384 + c0 + q * 4] = v;
    }
}

// ============================================================
// Kernel D: proj as mma.sync GEMM + BN2 + residual. (R12)
// ============================================================
__global__ void __launch_bounds__(256) proj_mma_kernel(
    const float* __restrict__ g2, const float* __restrict__ b2v,
    const float* __restrict__ x, float* __restrict__ out)
{
    extern __shared__ u32 smu[];
    const u32 sbase = smem_u32(smu);
    const int tid = threadIdx.x;
    const int wid = tid >> 5, lane = tid & 31;
    const int g = lane >> 2, t = lane & 3;
    const int wm = wid >> 1, wn = wid & 1;
    const int bx = blockIdx.x;
    const int ot = bx >> 7;
    const int nt = bx & 127;
    const int obase = ot * 128;
    const int img = nt >> 3;
    const int hw0 = (nt & 7) * 128;
    const u16* Asrc = g_wp3;
    const u16* Bsrc = g_sp3T + ((size_t)img * 1024 + hw0) * 384;

    float acc[2][8][4];
#pragma unroll
    for (int mt = 0; mt < 2; mt++)
#pragma unroll
        for (int ntt = 0; ntt < 8; ntt++)
#pragma unroll
            for (int q = 0; q < 4; q++) acc[mt][ntt][q] = 0.0f;

    auto ldChunk = [&](int c, int buf) {
        u32 sb = sbase + buf * 40960;
        int k0 = c * 32;
#pragma unroll
        for (int it = 0; it < 6; it++) {
            int e = tid + 256 * it;
            int j = e >> 9;
            int r = (e >> 2) & 127;
            int kg = e & 3;
            cp16(sb + (j * 2560 + r * 20 + kg * 4) * 4,
                 &Asrc[(size_t)j * 147456 + (size_t)(obase + r) * 384 + k0 + kg * 8]);
        }
#pragma unroll
        for (int it = 0; it < 2; it++) {
            int e = tid + 256 * it;
            int r = e >> 2, kg = e & 3;
            cp16(sb + (7680 + r * 20 + kg * 4) * 4,
                 &Bsrc[(size_t)r * 384 + k0 + kg * 8]);
        }
        CP_COMMIT();
    };

    const int aRow = wm * 32 + (lane & 15);
    const int aColw = ((lane >> 4) & 1) * 4;
    const int bRowB = wn * 64 + ((lane >> 4) & 1) * 8 + (lane & 7);
    const int bColw = ((lane >> 3) & 1) * 4;

    ldChunk(0, 0);
    for (int c = 0; c < 12; c++) {
        int buf = c & 1;
        if (c + 1 < 12) { ldChunk(c + 1, buf ^ 1); CP_WAIT1(); }
        else            { CP_WAIT0(); }
        __syncthreads();
        u32 soff = sbase + buf * 40960;
#pragma unroll
        for (int k16 = 0; k16 < 2; k16++) {
            u32 bfr[8][2];
#pragma unroll
            for (int p = 0; p < 4; p++) {
                u32 addr = soff + ((7680 + (bRowB + p * 16) * 20 + k16 * 8 + bColw) << 2);
                ldm_x4(bfr[2 * p][0], bfr[2 * p][1],
                       bfr[2 * p + 1][0], bfr[2 * p + 1][1], addr);
            }
#pragma unroll
            for (int j = 0; j < 3; j++) {
#pragma unroll
                for (int mt = 0; mt < 2; mt++) {
                    u32 addr = soff + ((j * 2560 + (aRow + mt * 16) * 20 + k16 * 8 + aColw) << 2);
                    u32 a0, a1, a2, a3;
                    ldm_x4(a0, a1, a2, a3, addr);
#pragma unroll
                    for (int ntt = 0; ntt < 8; ntt++)
                        mma16816(acc[mt][ntt][0], acc[mt][ntt][1],
                                 acc[mt][ntt][2], acc[mt][ntt][3],
                                 a0, a1, a2, a3, bfr[ntt][0], bfr[ntt][1]);
                }
            }
        }
        __syncthreads();
    }

    const float rs = rsqrtf(1.0f + EPSF);
#pragma unroll
    for (int mt = 0; mt < 2; mt++) {
        int o0 = obase + wm * 32 + mt * 16 + g;
        int o1 = o0 + 8;
        float bn0 = g2[o0] * rs, bt0 = b2v[o0];
        float bn1 = g2[o1] * rs, bt1 = b2v[o1];
#pragma unroll
        for (int ntt = 0; ntt < 8; ntt++) {
            int col = hw0 + wn * 64 + ntt * 8 + 2 * t;
            size_t i0 = ((size_t)img * 384 + o0) * 1024 + col;
            size_t i1 = ((size_t)img * 384 + o1) * 1024 + col;
            float2 x0 = *(const float2*)&x[i0];
            float2 x1 = *(const float2*)&x[i1];
            *(float2*)&out[i0] = make_float2(acc[mt][ntt][0] * bn0 + bt0 + x0.x,
                                             acc[mt][ntt][1] * bn0 + bt0 + x0.y);
            *(float2*)&out[i1] = make_float2(acc[mt][ntt][2] * bn1 + bt1 + x1.x,
                                             acc[mt][ntt][3] * bn1 + bt1 + x1.y);
        }
    }
}

// ============================================================
extern "C" void kernel_launch(void* const* d_in, const int* in_sizes, int n_in,
                              void* d_out, int out_size) {
    const float* x   = (const float*)d_in[0];
    const float* Wc  = (const float*)d_in[1];
    const float* g1  = (const float*)d_in[2];
    const float* b1  = (const float*)d_in[3];
    const float* Wp  = (const float*)d_in[4];
    const float* g2  = (const float*)d_in[5];
    const float* b2  = (const float*)d_in[6];
    const float* frx = (const float*)d_in[7];
    const float* fra = (const float*)d_in[8];
    float* out = (float*)d_out;

    const int smem_attn = 28672 * 4;   // 114,688 B (2 CTA/SM)
    const int smem_mma  = 81920;       // 2 x 40KB double buffer
    cudaFuncSetAttribute(attn_fused_kernel,
                         cudaFuncAttributeMaxDynamicSharedMemorySize, smem_attn);
    cudaFuncSetAttribute(conv_mma_kernel,
                         cudaFuncAttributeMaxDynamicSharedMemorySize, smem_mma);
    cudaFuncSetAttribute(proj_mma_kernel,
                         cudaFuncAttributeMaxDynamicSharedMemorySize, smem_mma);

    lif1_kernel<<<6144, 256>>>(x);
    im2col_kernel<<<6144, 256>>>();
    wsplit_kernel<<<5184, 256>>>(Wc, Wp);
    conv_mma_kernel<<<576, 256, smem_mma>>>();
    reduce_split_kernel<<<192, 256>>>(g1, b1);
    attn_fused_kernel<<<1536, 256, smem_attn>>>(frx, fra);
    transpose_sp3_kernel<<<1536, 256>>>();
    proj_mma_kernel<<<384, 256, smem_mma>>>(g2, b2, x, out);
}

// round 16
// speedup vs baseline: 1.0005x; 1.0005x over previous
#include <cuda_runtime.h>
#include <cuda_bf16.h>

#define EPSF 1e-5f
typedef unsigned short u16;
typedef unsigned int u32;
typedef unsigned long long u64;

// ---------------- device scratch ----------------
static __device__ __align__(256) float g_xs  [6291456];   // LIF1 spikes f32 [img][c][hw]
static __device__ __align__(256) u16   g_xsb [6291456];   // conv B bf16 im2col [img][p][k]
static __device__ __align__(256) float g_y   [3145728];   // conv+BN y1 rows [img][768][256]
static __device__ __align__(256) float g_y2T [1572864];   // y2 BN'd transposed [img][h][n=256][d=32]
static __device__ __align__(256) float g_yp  [3][3145728];// conv K-split partials
static __device__ __align__(256) u16   g_sp3b[6291456];   // LIF3 spikes bf16 [img][c][hw]
static __device__ __align__(256) u16   g_sp3T[6291456];   // transposed [img][hw][c]
static __device__ __align__(256) u16   g_wc3 [3538944];   // Wconv 3-term bf16 [3][768][1536]
static __device__ __align__(256) u16   g_wp3 [442368];    // Wproj 3-term bf16 [3][384][384]

// ---------------- fp32x2 helpers ----------------
__device__ __forceinline__ u64 pk2(float lo, float hi) {
    u64 r; asm("mov.b64 %0, {%1,%2};" : "=l"(r) : "f"(lo), "f"(hi)); return r;
}
__device__ __forceinline__ void upk2(u64 v, float& lo, float& hi) {
    asm("mov.b64 {%0,%1}, %2;" : "=f"(lo), "=f"(hi) : "l"(v));
}
__device__ __forceinline__ u64 ffma2(u64 a, u64 b, u64 c) {
    u64 d; asm("fma.rn.f32x2 %0, %1, %2, %3;" : "=l"(d) : "l"(a), "l"(b), "l"(c)); return d;
}

// ---------------- mma / ldmatrix / cp.async helpers ----------------
__device__ __forceinline__ void mma16816(
    float& c0, float& c1, float& c2, float& c3,
    u32 a0, u32 a1, u32 a2, u32 a3, u32 b0, u32 b1)
{
    asm volatile(
        "mma.sync.aligned.m16n8k16.row.col.f32.bf16.bf16.f32 "
        "{%0,%1,%2,%3}, {%4,%5,%6,%7}, {%8,%9}, {%0,%1,%2,%3};"
        : "+f"(c0), "+f"(c1), "+f"(c2), "+f"(c3)
        : "r"(a0), "r"(a1), "r"(a2), "r"(a3), "r"(b0), "r"(b1));
}
__device__ __forceinline__ void ldm_x4(u32& r0, u32& r1, u32& r2, u32& r3, u32 addr) {
    asm volatile("ldmatrix.sync.aligned.m8n8.x4.shared.b16 {%0,%1,%2,%3}, [%4];"
                 : "=r"(r0), "=r"(r1), "=r"(r2), "=r"(r3) : "r"(addr));
}
__device__ __forceinline__ void cp16(u32 saddr, const void* g) {
    asm volatile("cp.async.cg.shared.global [%0], [%1], 16;" :: "r"(saddr), "l"(g));
}
#define CP_COMMIT() asm volatile("cp.async.commit_group;" ::: "memory")
#define CP_WAIT1()  asm volatile("cp.async.wait_group 1;" ::: "memory")
#define CP_WAIT0()  asm volatile("cp.async.wait_group 0;" ::: "memory")
__device__ __forceinline__ u32 smem_u32(const void* p) {
    u32 a;
    asm("{ .reg .u64 t; cvta.to.shared.u64 t, %1; cvt.u32.u64 %0, t; }" : "=r"(a) : "l"(p));
    return a;
}
__device__ __forceinline__ void split3(float w, u16& h0, u16& m0, u16& l0) {
    __nv_bfloat16 hh = __float2bfloat16(w);
    float r1 = w - __bfloat162float(hh);
    __nv_bfloat16 mm = __float2bfloat16(r1);
    float r2 = r1 - __bfloat162float(mm);
    h0 = __bfloat16_as_ushort(hh);
    m0 = __bfloat16_as_ushort(mm);
    l0 = __bfloat16_as_ushort(__float2bfloat16(r2));
}

// ============================================================
// Kernel A: LIF over T on x -> spikes g_xs (f32)
// ============================================================
__global__ void __launch_bounds__(256) lif1_kernel(const float* __restrict__ x) {
    const int S = 4 * 384 * 1024;
    int i = blockIdx.x * blockDim.x + threadIdx.x;
    float v = 0.0f;
#pragma unroll
    for (int t = 0; t < 4; t++) {
        v = 0.5f * (v + x[(size_t)t * S + i]);
        bool s = (v >= 1.0f);
        g_xs[(size_t)t * S + i] = s ? 1.0f : 0.0f;
        v = s ? 0.0f : v;
    }
}

// ============================================================
// Kernel A2: im2col bf16 for conv B
// ============================================================
__global__ void __launch_bounds__(256) im2col_kernel() {
    int idx = blockIdx.x * 256 + threadIdx.x;
    int img = idx / 98304;
    int r = idx - img * 98304;
    int c = r >> 8;
    int pp = r & 255;
    int ii = pp >> 4, jj = pp & 15;
    const float* base = g_xs + (size_t)img * 393216 + c * 1024;
    float2 a = *(const float2*)&base[(2 * ii) * 32 + 2 * jj];
    float2 b = *(const float2*)&base[(2 * ii + 1) * 32 + 2 * jj];
    ushort4 o;
    o.x = (a.x > 0.5f) ? 0x3F80 : 0;
    o.y = (a.y > 0.5f) ? 0x3F80 : 0;
    o.z = (b.x > 0.5f) ? 0x3F80 : 0;
    o.w = (b.y > 0.5f) ? 0x3F80 : 0;
    *(ushort4*)&g_xsb[((size_t)img * 256 + pp) * 1536 + c * 4] = o;
}

// ============================================================
// Kernel W: split fp32 weights into 3 bf16 terms (Dekker, exact)
// ============================================================
__global__ void __launch_bounds__(256) wsplit_kernel(
    const float* __restrict__ Wc, const float* __restrict__ Wp)
{
    int i = blockIdx.x * 256 + threadIdx.x;
    float w;
    u16* d;
    int n, off;
    if (i < 1179648) { off = i; w = Wc[off]; d = g_wc3; n = 1179648; }
    else             { off = i - 1179648; w = Wp[off]; d = g_wp3; n = 147456; }
    u16 h0, m0, l0;
    split3(w, h0, m0, l0);
    d[off]         = h0;
    d[n + off]     = m0;
    d[2 * n + off] = l0;
}

// ============================================================
// Kernel B: conv as mma.sync GEMM, K-split 3 -> fp32 partials.
// (unchanged from R12 measured 84.3us)
// ============================================================
__global__ void __launch_bounds__(256) conv_mma_kernel()
{
    extern __shared__ u32 smu[];
    const u32 sbase = smem_u32(smu);
    const int tid = threadIdx.x;
    const int wid = tid >> 5, lane = tid & 31;
    const int g = lane >> 2, t = lane & 3;
    const int wm = wid >> 1, wn = wid & 1;
    const int bx = blockIdx.x;
    const int ks = bx / 192;
    const int rem = bx % 192;
    const int img = rem / 12;
    const int r12 = rem % 12;
    const int ot = r12 >> 1, pt = r12 & 1;
    const int obase = ot * 128, pbase = pt * 128;
    const int kbase = ks * 512;
    const u16* Asrc = g_wc3;
    const u16* Bsrc = g_xsb + ((size_t)img * 256 + pbase) * 1536;

    float acc[2][8][4];
#pragma unroll
    for (int mt = 0; mt < 2; mt++)
#pragma unroll
        for (int nt = 0; nt < 8; nt++)
#pragma unroll
            for (int q = 0; q < 4; q++) acc[mt][nt][q] = 0.0f;

    auto ldChunk = [&](int c, int buf) {
        u32 sb = sbase + buf * 40960;
        int k0 = kbase + c * 32;
#pragma unroll
        for (int it = 0; it < 6; it++) {
            int e = tid + 256 * it;
            int j = e >> 9;
            int r = (e >> 2) & 127;
            int kg = e & 3;
            cp16(sb + (j * 2560 + r * 20 + kg * 4) * 4,
                 &Asrc[(size_t)j * 1179648 + (size_t)(obase + r) * 1536 + k0 + kg * 8]);
        }
#pragma unroll
        for (int it = 0; it < 2; it++) {
            int e = tid + 256 * it;
            int r = e >> 2, kg = e & 3;
            cp16(sb + (7680 + r * 20 + kg * 4) * 4,
                 &Bsrc[(size_t)r * 1536 + k0 + kg * 8]);
        }
        CP_COMMIT();
    };

    const int aRow = wm * 32 + (lane & 15);
    const int aColw = ((lane >> 4) & 1) * 4;
    const int bRowB = wn * 64 + ((lane >> 4) & 1) * 8 + (lane & 7);
    const int bColw = ((lane >> 3) & 1) * 4;

    ldChunk(0, 0);
    for (int c = 0; c < 16; c++) {
        int buf = c & 1;
        if (c + 1 < 16) { ldChunk(c + 1, buf ^ 1); CP_WAIT1(); }
        else            { CP_WAIT0(); }
        __syncthreads();
        u32 soff = sbase + buf * 40960;
#pragma unroll
        for (int k16 = 0; k16 < 2; k16++) {
            u32 bfr[8][2];
#pragma unroll
            for (int p = 0; p < 4; p++) {
                u32 addr = soff + ((7680 + (bRowB + p * 16) * 20 + k16 * 8 + bColw) << 2);
                ldm_x4(bfr[2 * p][0], bfr[2 * p][1],
                       bfr[2 * p + 1][0], bfr[2 * p + 1][1], addr);
            }
#pragma unroll
            for (int j = 0; j < 3; j++) {
#pragma unroll
                for (int mt = 0; mt < 2; mt++) {
                    u32 addr = soff + ((j * 2560 + (aRow + mt * 16) * 20 + k16 * 8 + aColw) << 2);
                    u32 a0, a1, a2, a3;
                    ldm_x4(a0, a1, a2, a3, addr);
#pragma unroll
                    for (int nt = 0; nt < 8; nt++)
                        mma16816(acc[mt][nt][0], acc[mt][nt][1],
                                 acc[mt][nt][2], acc[mt][nt][3],
                                 a0, a1, a2, a3, bfr[nt][0], bfr[nt][1]);
                }
            }
        }
        __syncthreads();
    }

    float* yo = g_yp[ks];
#pragma unroll
    for (int mt = 0; mt < 2; mt++) {
        int o0 = obase + wm * 32 + mt * 16 + g;
        int o1 = o0 + 8;
#pragma unroll
        for (int nt = 0; nt < 8; nt++) {
            int p = pbase + wn * 64 + nt * 8 + 2 * t;
            *(float2*)&yo[((size_t)img * 768 + o0) * 256 + p] =
                make_float2(acc[mt][nt][0], acc[mt][nt][1]);
            *(float2*)&yo[((size_t)img * 768 + o1) * 256 + p] =
                make_float2(acc[mt][nt][2], acc[mt][nt][3]);
        }
    }
}

// ============================================================
// Kernel B2: reduce partials + BN1.
// y1 rows -> g_y (layout unchanged); y2 rows -> g_y2T transposed.
// grid 192 (img*12+h), 256 thr.
// ============================================================
__global__ void __launch_bounds__(256) reduce_split_kernel(
    const float* __restrict__ g1, const float* __restrict__ b1)
{
    __shared__ float ts[32 * 260];
    const int bx = blockIdx.x;
    const int img = bx / 12;
    const int h = bx % 12;
    const int tid = threadIdx.x;
    const float rs = rsqrtf(1.0f + EPSF);

    // Phase A: y1 rows (o = h*64 + 0..31) -> g_y (same layout)
#pragma unroll
    for (int it = 0; it < 8; it++) {
        int e = it * 256 + tid;
        int dd = e >> 6, n4 = (e & 63) * 4;
        int o = h * 64 + dd;
        size_t idx = ((size_t)img * 768 + o) * 256 + n4;
        float4 a = *(const float4*)&g_yp[0][idx];
        float4 b = *(const float4*)&g_yp[1][idx];
        float4 c = *(const float4*)&g_yp[2][idx];
        float bn = g1[o] * rs, bt = b1[o];
        *(float4*)&g_y[idx] = make_float4(
            (a.x + b.x + c.x) * bn + bt, (a.y + b.y + c.y) * bn + bt,
            (a.z + b.z + c.z) * bn + bt, (a.w + b.w + c.w) * bn + bt);
    }
    // Phase B: y2 rows (o = h*64 + 32 + dd) -> smem tile -> g_y2T [n][d]
#pragma unroll
    for (int it = 0; it < 8; it++) {
        int e = it * 256 + tid;
        int dd = e >> 6, n4 = (e & 63) * 4;
        int o = h * 64 + 32 + dd;
        size_t idx = ((size_t)img * 768 + o) * 256 + n4;
        float4 a = *(const float4*)&g_yp[0][idx];
        float4 b = *(const float4*)&g_yp[1][idx];
        float4 c = *(const float4*)&g_yp[2][idx];
        float bn = g1[o] * rs, bt = b1[o];
        *(float4*)&ts[dd * 260 + n4] = make_float4(
            (a.x + b.x + c.x) * bn + bt, (a.y + b.y + c.y) * bn + bt,
            (a.z + b.z + c.z) * bn + bt, (a.w + b.w + c.w) * bn + bt);
    }
    __syncthreads();
    // write transposed: thread tid owns column n=tid
    {
        float col[32];
#pragma unroll
        for (int d = 0; d < 32; d++) col[d] = ts[d * 260 + tid];
        float* dst = &g_y2T[(((size_t)img * 12 + h) * 256 + tid) * 32];
#pragma unroll
        for (int q = 0; q < 8; q++)
            *(float4*)&dst[q * 4] = make_float4(col[4 * q], col[4 * q + 1],
                                                col[4 * q + 2], col[4 * q + 3]);
    }
}

// ============================================================
// Kernel C: fused attn GEMM -> LIF2 -> out GEMM(ksplit8) -> LIF3
// y2 transposed [n][d] -> GEMM2 fragment loads hit 1 line.
// smem (floats): y1s[32][256]@0 | xr[2][32][32]@8192 |
//   y2T[256][36]@10240 | ss/sp[9216]@19456  -> 114,688 B
// ============================================================
__global__ void __launch_bounds__(256, 2) attn_fused_kernel(
    const float* __restrict__ frx, const float* __restrict__ fra)
{
    extern __shared__ __align__(16) float sm[];
    float* y1s = sm;
    float* y2T = sm + 10240;
    float* ss  = sm + 19456;
    float* sp  = sm + 19456;   // overlay on ss (post-GEMM2)
    const u32 sbase = smem_u32(sm);

    const int bx = blockIdx.x;
    const int mt = bx & 31;
    const int h  = (bx >> 5) % 12;
    const int b  = bx / 384;
    const int tid = threadIdx.x;

    const int ng = tid >> 2;
    const int mg = tid & 3;
    const int n0 = ng * 4, m0 = mg * 8;
    const int kg = tid >> 5;
    const int lane = tid & 31;
    const int dg = lane >> 2;          // GEMM2 d-tile = 4*dg .. 4*dg+3
    const int mq = lane & 3;
    const int rd = tid >> 3;
    const int rm = (tid & 7) * 4;

    const float scale1 = rsqrtf(frx[h] * 32.0f);
    const float scale2 = rsqrtf(fra[h] * 256.0f);

    float v2[4][8];
    float v3[4];
#pragma unroll
    for (int i = 0; i < 4; i++)
#pragma unroll
        for (int j = 0; j < 8; j++) v2[i][j] = 0.0f;
#pragma unroll
    for (int i = 0; i < 4; i++) v3[i] = 0.0f;

    auto issue_y1 = [&](int img) {
        const float* ybase = g_y + ((size_t)img * 768 + h * 64) * 256;
#pragma unroll
        for (int r = 0; r < 8; r++) {
            int e = tid + 256 * r;
            int d = e >> 6, c4 = (e & 63) * 4;
            cp16(sbase + (u32)(d * 256 + c4) * 4, &ybase[d * 256 + c4]);
        }
        CP_COMMIT();
    };
    auto issue_y2 = [&](int img) {
        const float* ybase = g_y2T + (((size_t)img * 12 + h) * 256) * 32;
#pragma unroll
        for (int r = 0; r < 8; r++) {
            int e = tid + 256 * r;
            int rr = e >> 3, ch = (e & 7) * 4;
            cp16(sbase + (u32)(10240 + rr * 36 + ch) * 4, &ybase[rr * 32 + ch]);
        }
        CP_COMMIT();
    };
    auto load_xr = [&](int img, int buf) {
        const float* xbase = g_xs + ((size_t)img * 384 + h * 32) * 1024 + mt * 32;
        int d = tid >> 3, c4 = (tid & 7) * 4;
        float4 v = *(const float4*)&xbase[d * 1024 + c4];
        float* dst = sm + 8192 + buf * 1024;
        *(float4*)&dst[d * 32 + c4] = make_float4(
            v.x * scale1, v.y * scale1, v.z * scale1, v.w * scale1);
    };

    issue_y1(b);
    issue_y2(b);
    load_xr(b, 0);

    for (int t = 0; t < 4; t++) {
        const int img = t * 4 + b;
        CP_WAIT0();
        __syncthreads();
        if (t < 3) load_xr(img + 4, (t + 1) & 1);
        const float* xrs = sm + 8192 + (t & 1) * 1024;

        // GEMM1
        u64 acc[4][4];
#pragma unroll
        for (int i = 0; i < 4; i++)
#pragma unroll
            for (int q = 0; q < 4; q++) acc[i][q] = pk2(v2[i][2 * q], v2[i][2 * q + 1]);
#pragma unroll 8
        for (int d = 0; d < 32; d++) {
            float4 a4 = *(const float4*)&y1s[d * 256 + n0];
            ulonglong2 x0 = *(const ulonglong2*)&xrs[d * 32 + m0];
            ulonglong2 x1 = *(const ulonglong2*)&xrs[d * 32 + m0 + 4];
            float av[4] = {a4.x, a4.y, a4.z, a4.w};
#pragma unroll
            for (int i = 0; i < 4; i++) {
                u64 ar = pk2(av[i], av[i]);
                acc[i][0] = ffma2(ar, x0.x, acc[i][0]);
                acc[i][1] = ffma2(ar, x0.y, acc[i][1]);
                acc[i][2] = ffma2(ar, x1.x, acc[i][2]);
                acc[i][3] = ffma2(ar, x1.y, acc[i][3]);
            }
        }
        // LIF2 (spikes stored as scale2 / 0; bit-exact commuted product)
#pragma unroll
        for (int i = 0; i < 4; i++) {
            float s[8];
#pragma unroll
            for (int q = 0; q < 4; q++) {
                float lo, hi;
                upk2(acc[i][q], lo, hi);
                lo *= 0.5f; hi *= 0.5f;
                s[2 * q]     = (lo >= 1.0f) ? scale2 : 0.0f;
                s[2 * q + 1] = (hi >= 1.0f) ? scale2 : 0.0f;
                v2[i][2 * q]     = (lo >= 1.0f) ? 0.0f : lo;
                v2[i][2 * q + 1] = (hi >= 1.0f) ? 0.0f : hi;
            }
            *(float4*)&ss[(n0 + i) * 36 + m0]     = make_float4(s[0], s[1], s[2], s[3]);
            *(float4*)&ss[(n0 + i) * 36 + m0 + 4] = make_float4(s[4], s[5], s[6], s[7]);
        }
        __syncthreads();
        if (t < 3) issue_y1(img + 4);

        // GEMM2 (ksplit 8): thread tile d = 4*dg..+3, m = mq*8..+7
        u64 acc2[4][4];
#pragma unroll
        for (int i = 0; i < 4; i++)
#pragma unroll
            for (int q = 0; q < 4; q++) acc2[i][q] = 0ull;
#pragma unroll
        for (int nn = 0; nn < 32; nn += 4) {
            int n = kg * 32 + nn;
            float4 yv0 = *(const float4*)&y2T[(n + 0) * 36 + dg * 4];
            float4 yv1 = *(const float4*)&y2T[(n + 1) * 36 + dg * 4];
            float4 yv2 = *(const float4*)&y2T[(n + 2) * 36 + dg * 4];
            float4 yv3 = *(const float4*)&y2T[(n + 3) * 36 + dg * 4];
            float bv[4][4] = {{yv0.x, yv0.y, yv0.z, yv0.w}, {yv1.x, yv1.y, yv1.z, yv1.w},
                              {yv2.x, yv2.y, yv2.z, yv2.w}, {yv3.x, yv3.y, yv3.z, yv3.w}};
#pragma unroll
            for (int j = 0; j < 4; j++) {
                ulonglong2 s0 = *(const ulonglong2*)&ss[(n + j) * 36 + mq * 8];
                ulonglong2 s1 = *(const ulonglong2*)&ss[(n + j) * 36 + mq * 8 + 4];
#pragma unroll
                for (int i = 0; i < 4; i++) {
                    u64 ar = pk2(bv[j][i], bv[j][i]);
                    acc2[i][0] = ffma2(ar, s0.x, acc2[i][0]);
                    acc2[i][1] = ffma2(ar, s0.y, acc2[i][1]);
                    acc2[i][2] = ffma2(ar, s1.x, acc2[i][2]);
                    acc2[i][3] = ffma2(ar, s1.y, acc2[i][3]);
                }
            }
        }
        __syncthreads();
        if (t < 3) issue_y2(img + 4);
#pragma unroll
        for (int i = 0; i < 4; i++) {
            float* dst = &sp[kg * 1152 + (4 * dg + i) * 36 + mq * 8];
            *(ulonglong2*)dst       = make_ulonglong2(acc2[i][0], acc2[i][1]);
            *(ulonglong2*)(dst + 4) = make_ulonglong2(acc2[i][2], acc2[i][3]);
        }
        __syncthreads();

        // reduce + LIF3 + bf16 spike store
        float4 sum = make_float4(v3[0], v3[1], v3[2], v3[3]);
#pragma unroll
        for (int k = 0; k < 8; k++) {
            float4 p = *(const float4*)&sp[k * 1152 + rd * 36 + rm];
            sum.x += p.x; sum.y += p.y; sum.z += p.z; sum.w += p.w;
        }
        sum.x *= 0.5f; sum.y *= 0.5f; sum.z *= 0.5f; sum.w *= 0.5f;
        ushort4 sb;
        sb.x = (sum.x >= 1.0f) ? 0x3F80 : 0; v3[0] = (sum.x >= 1.0f) ? 0.0f : sum.x;
        sb.y = (sum.y >= 1.0f) ? 0x3F80 : 0; v3[1] = (sum.y >= 1.0f) ? 0.0f : sum.y;
        sb.z = (sum.z >= 1.0f) ? 0x3F80 : 0; v3[2] = (sum.z >= 1.0f) ? 0.0f : sum.z;
        sb.w = (sum.w >= 1.0f) ? 0x3F80 : 0; v3[3] = (sum.w >= 1.0f) ? 0.0f : sum.w;
        *(ushort4*)&g_sp3b[((size_t)img * 384 + h * 32 + rd) * 1024 + mt * 32 + rm] = sb;
        __syncthreads();
    }
}

// ============================================================
// Kernel T: transpose bf16 spikes [c][hw] -> [hw][c] per img
// ============================================================
__global__ void __launch_bounds__(256) transpose_sp3_kernel() {
    __shared__ u16 ts[64][72];
    int bx = blockIdx.x;
    int img = bx / 96;
    int r = bx % 96;
    int c0 = (r / 16) * 64;
    int hw0 = (r % 16) * 64;
    int tid = threadIdx.x;
#pragma unroll
    for (int it = 0; it < 4; it++) {
        int e = tid + 256 * it;
        int row = e >> 4, q = e & 15;
        u64 v = *(const u64*)&g_sp3b[((size_t)img * 384 + c0 + row) * 1024 + hw0 + q * 4];
        *(u64*)&ts[row][q * 4] = v;
    }
    __syncthreads();
#pragma unroll
    for (int it = 0; it < 4; it++) {
        int e = tid + 256 * it;
        int orow = e >> 4, q = e & 15;
        u64 v = (u64)ts[q * 4 + 0][orow]
              | ((u64)ts[q * 4 + 1][orow] << 16)
              | ((u64)ts[q * 4 + 2][orow] << 32)
              | ((u64)ts[q * 4 + 3][orow] << 48);
        *(u64*)&g_sp3T[((size_t)img * 1024 + hw0 + orow) * 384 + c0 + q * 4] = v;
    }
}

// ============================================================
// Kernel D: proj as mma.sync GEMM + BN2 + residual. (R12)
// ============================================================
__global__ void __launch_bounds__(256) proj_mma_kernel(
    const float* __restrict__ g2, const float* __restrict__ b2v,
    const float* __restrict__ x, float* __restrict__ out)
{
    extern __shared__ u32 smu[];
    const u32 sbase = smem_u32(smu);
    const int tid = threadIdx.x;
    const int wid = tid >> 5, lane = tid & 31;
    const int g = lane >> 2, t = lane & 3;
    const int wm = wid >> 1, wn = wid & 1;
    const int bx = blockIdx.x;
    const int ot = bx >> 7;
    const int nt = bx & 127;
    const int obase = ot * 128;
    const int img = nt >> 3;
    const int hw0 = (nt & 7) * 128;
    const u16* Asrc = g_wp3;
    const u16* Bsrc = g_sp3T + ((size_t)img * 1024 + hw0) * 384;

    float acc[2][8][4];
#pragma unroll
    for (int mt = 0; mt < 2; mt++)
#pragma unroll
        for (int ntt = 0; ntt < 8; ntt++)
#pragma unroll
            for (int q = 0; q < 4; q++) acc[mt][ntt][q] = 0.0f;

    auto ldChunk = [&](int c, int buf) {
        u32 sb = sbase + buf * 40960;
        int k0 = c * 32;
#pragma unroll
        for (int it = 0; it < 6; it++) {
            int e = tid + 256 * it;
            int j = e >> 9;
            int r = (e >> 2) & 127;
            int kg = e & 3;
            cp16(sb + (j * 2560 + r * 20 + kg * 4) * 4,
                 &Asrc[(size_t)j * 147456 + (size_t)(obase + r) * 384 + k0 + kg * 8]);
        }
#pragma unroll
        for (int it = 0; it < 2; it++) {
            int e = tid + 256 * it;
            int r = e >> 2, kg = e & 3;
            cp16(sb + (7680 + r * 20 + kg * 4) * 4,
                 &Bsrc[(size_t)r * 384 + k0 + kg * 8]);
        }
        CP_COMMIT();
    };

    const int aRow = wm * 32 + (lane & 15);
    const int aColw = ((lane >> 4) & 1) * 4;
    const int bRowB = wn * 64 + ((lane >> 4) & 1) * 8 + (lane & 7);
    const int bColw = ((lane >> 3) & 1) * 4;

    ldChunk(0, 0);
    for (int c = 0; c < 12; c++) {
        int buf = c & 1;
        if (c + 1 < 12) { ldChunk(c + 1, buf ^ 1); CP_WAIT1(); }
        else            { CP_WAIT0(); }
        __syncthreads();
        u32 soff = sbase + buf * 40960;
#pragma unroll
        for (int k16 = 0; k16 < 2; k16++) {
            u32 bfr[8][2];
#pragma unroll
            for (int p = 0; p < 4; p++) {
                u32 addr = soff + ((7680 + (bRowB + p * 16) * 20 + k16 * 8 + bColw) << 2);
                ldm_x4(bfr[2 * p][0], bfr[2 * p][1],
                       bfr[2 * p + 1][0], bfr[2 * p + 1][1], addr);
            }
#pragma unroll
            for (int j = 0; j < 3; j++) {
#pragma unroll
                for (int mt = 0; mt < 2; mt++) {
                    u32 addr = soff + ((j * 2560 + (aRow + mt * 16) * 20 + k16 * 8 + aColw) << 2);
                    u32 a0, a1, a2, a3;
                    ldm_x4(a0, a1, a2, a3, addr);
#pragma unroll
                    for (int ntt = 0; ntt < 8; ntt++)
                        mma16816(acc[mt][ntt][0], acc[mt][ntt][1],
                                 acc[mt][ntt][2], acc[mt][ntt][3],
                                 a0, a1, a2, a3, bfr[ntt][0], bfr[ntt][1]);
                }
            }
        }
        __syncthreads();
    }

    const float rs = rsqrtf(1.0f + EPSF);
#pragma unroll
    for (int mt = 0; mt < 2; mt++) {
        int o0 = obase + wm * 32 + mt * 16 + g;
        int o1 = o0 + 8;
        float bn0 = g2[o0] * rs, bt0 = b2v[o0];
        float bn1 = g2[o1] * rs, bt1 = b2v[o1];
#pragma unroll
        for (int ntt = 0; ntt < 8; ntt++) {
            int col = hw0 + wn * 64 + ntt * 8 + 2 * t;
            size_t i0 = ((size_t)img * 384 + o0) * 1024 + col;
            size_t i1 = ((size_t)img * 384 + o1) * 1024 + col;
            float2 x0 = *(const float2*)&x[i0];
            float2 x1 = *(const float2*)&x[i1];
            *(float2*)&out[i0] = make_float2(acc[mt][ntt][0] * bn0 + bt0 + x0.x,
                                             acc[mt][ntt][1] * bn0 + bt0 + x0.y);
            *(float2*)&out[i1] = make_float2(acc[mt][ntt][2] * bn1 + bt1 + x1.x,
                                             acc[mt][ntt][3] * bn1 + bt1 + x1.y);
        }
    }
}

// ============================================================
extern "C" void kernel_launch(void* const* d_in, const int* in_sizes, int n_in,
                              void* d_out, int out_size) {
    const float* x   = (const float*)d_in[0];
    const float* Wc  = (const float*)d_in[1];
    const float* g1  = (const float*)d_in[2];
    const float* b1  = (const float*)d_in[3];
    const float* Wp  = (const float*)d_in[4];
    const float* g2  = (const float*)d_in[5];
    const float* b2  = (const float*)d_in[6];
    const float* frx = (const float*)d_in[7];
    const float* fra = (const float*)d_in[8];
    float* out = (float*)d_out;

    const int smem_attn = 28672 * 4;   // 114,688 B (2 CTA/SM)
    const int smem_mma  = 81920;       // 2 x 40KB double buffer
    cudaFuncSetAttribute(attn_fused_kernel,
                         cudaFuncAttributeMaxDynamicSharedMemorySize, smem_attn);
    cudaFuncSetAttribute(conv_mma_kernel,
                         cudaFuncAttributeMaxDynamicSharedMemorySize, smem_mma);
    cudaFuncSetAttribute(proj_mma_kernel,
                         cudaFuncAttributeMaxDynamicSharedMemorySize, smem_mma);

    lif1_kernel<<<6144, 256>>>(x);
    im2col_kernel<<<6144, 256>>>();
    wsplit_kernel<<<5184, 256>>>(Wc, Wp);
    conv_mma_kernel<<<576, 256, smem_mma>>>();
    reduce_split_kernel<<<192, 256>>>(g1, b1);
    attn_fused_kernel<<<1536, 256, smem_attn>>>(frx, fra);
    transpose_sp3_kernel<<<1536, 256>>>();
    proj_mma_kernel<<<384, 256, smem_mma>>>(g2, b2, x, out);
}

// round 17
// speedup vs baseline: 1.0255x; 1.0250x over previous
#include <cuda_runtime.h>
#include <cuda_bf16.h>

#define EPSF 1e-5f
typedef unsigned short u16;
typedef unsigned int u32;
typedef unsigned long long u64;

// ---------------- device scratch ----------------
static __device__ __align__(256) u16   g_xs  [6291456];   // LIF1 spikes bf16 [img][c][hw]
static __device__ __align__(256) u16   g_xsb [6291456];   // conv B bf16 im2col [img][p][k]
static __device__ __align__(256) float g_y   [3145728];   // conv+BN output f32
static __device__ __align__(256) float g_yp  [3][3145728];// conv K-split partials
static __device__ __align__(256) u16   g_sp3b[6291456];   // LIF3 spikes bf16 [img][c][hw]
static __device__ __align__(256) u16   g_sp3T[6291456];   // transposed [img][hw][c]
static __device__ __align__(256) u16   g_wc3 [3538944];   // Wconv 3-term bf16 [3][768][1536]
static __device__ __align__(256) u16   g_wp3 [442368];    // Wproj 3-term bf16 [3][384][384]

// ---------------- fp32x2 helpers ----------------
__device__ __forceinline__ u64 pk2(float lo, float hi) {
    u64 r; asm("mov.b64 %0, {%1,%2};" : "=l"(r) : "f"(lo), "f"(hi)); return r;
}
__device__ __forceinline__ void upk2(u64 v, float& lo, float& hi) {
    asm("mov.b64 {%0,%1}, %2;" : "=f"(lo), "=f"(hi) : "l"(v));
}
__device__ __forceinline__ u64 ffma2(u64 a, u64 b, u64 c) {
    u64 d; asm("fma.rn.f32x2 %0, %1, %2, %3;" : "=l"(d) : "l"(a), "l"(b), "l"(c)); return d;
}

// ---------------- mma / ldmatrix / cp.async helpers ----------------
__device__ __forceinline__ void mma16816(
    float& c0, float& c1, float& c2, float& c3,
    u32 a0, u32 a1, u32 a2, u32 a3, u32 b0, u32 b1)
{
    asm volatile(
        "mma.sync.aligned.m16n8k16.row.col.f32.bf16.bf16.f32 "
        "{%0,%1,%2,%3}, {%4,%5,%6,%7}, {%8,%9}, {%0,%1,%2,%3};"
        : "+f"(c0), "+f"(c1), "+f"(c2), "+f"(c3)
        : "r"(a0), "r"(a1), "r"(a2), "r"(a3), "r"(b0), "r"(b1));
}
__device__ __forceinline__ void ldm_x4(u32& r0, u32& r1, u32& r2, u32& r3, u32 addr) {
    asm volatile("ldmatrix.sync.aligned.m8n8.x4.shared.b16 {%0,%1,%2,%3}, [%4];"
                 : "=r"(r0), "=r"(r1), "=r"(r2), "=r"(r3) : "r"(addr));
}
__device__ __forceinline__ void cp16(u32 saddr, const void* g) {
    asm volatile("cp.async.cg.shared.global [%0], [%1], 16;" :: "r"(saddr), "l"(g));
}
#define CP_COMMIT() asm volatile("cp.async.commit_group;" ::: "memory")
#define CP_WAIT0()  asm volatile("cp.async.wait_group 0;" ::: "memory")
__device__ __forceinline__ u32 smem_u32(const void* p) {
    u32 a;
    asm("{ .reg .u64 t; cvta.to.shared.u64 t, %1; cvt.u32.u64 %0, t; }" : "=r"(a) : "l"(p));
    return a;
}
__device__ __forceinline__ void split3(float w, u16& h0, u16& m0, u16& l0) {
    __nv_bfloat16 hh = __float2bfloat16(w);
    float r1 = w - __bfloat162float(hh);
    __nv_bfloat16 mm = __float2bfloat16(r1);
    float r2 = r1 - __bfloat162float(mm);
    h0 = __bfloat16_as_ushort(hh);
    m0 = __bfloat16_as_ushort(mm);
    l0 = __bfloat16_as_ushort(__float2bfloat16(r2));
}
__device__ __forceinline__ float bf16u_to_f32(u16 s) {
    return __uint_as_float(((u32)s) << 16);   // exact for all bf16
}

// ============================================================
// Kernel A: LIF over T on x -> spikes g_xs (bf16)
// ============================================================
__global__ void __launch_bounds__(256) lif1_kernel(const float* __restrict__ x) {
    const int S = 4 * 384 * 1024;
    int i = blockIdx.x * blockDim.x + threadIdx.x;
    float v = 0.0f;
#pragma unroll
    for (int t = 0; t < 4; t++) {
        v = 0.5f * (v + x[(size_t)t * S + i]);
        bool s = (v >= 1.0f);
        g_xs[(size_t)t * S + i] = s ? (u16)0x3F80 : (u16)0;
        v = s ? 0.0f : v;
    }
}

// ============================================================
// Kernel A2: im2col bf16 for conv B (reads bf16 spikes)
// ============================================================
__global__ void __launch_bounds__(256) im2col_kernel() {
    int idx = blockIdx.x * 256 + threadIdx.x;
    int img = idx / 98304;
    int r = idx - img * 98304;
    int c = r >> 8;
    int pp = r & 255;
    int ii = pp >> 4, jj = pp & 15;
    const u16* base = g_xs + (size_t)img * 393216 + c * 1024;
    u32 a = *(const u32*)&base[(2 * ii) * 32 + 2 * jj];
    u32 b = *(const u32*)&base[(2 * ii + 1) * 32 + 2 * jj];
    ushort4 o;
    o.x = (u16)(a & 0xFFFF);
    o.y = (u16)(a >> 16);
    o.z = (u16)(b & 0xFFFF);
    o.w = (u16)(b >> 16);
    *(ushort4*)&g_xsb[((size_t)img * 256 + pp) * 1536 + c * 4] = o;
}

// ============================================================
// Kernel W: split fp32 weights into 3 bf16 terms (Dekker, exact)
// ============================================================
__global__ void __launch_bounds__(256) wsplit_kernel(
    const float* __restrict__ Wc, const float* __restrict__ Wp)
{
    int i = blockIdx.x * 256 + threadIdx.x;
    float w;
    u16* d;
    int n, off;
    if (i < 1179648) { off = i; w = Wc[off]; d = g_wc3; n = 1179648; }
    else             { off = i - 1179648; w = Wp[off]; d = g_wp3; n = 147456; }
    u16 h0, m0, l0;
    split3(w, h0, m0, l0);
    d[off]         = h0;
    d[n + off]     = m0;
    d[2 * n + off] = l0;
}

// ============================================================
// Kernel B: conv as mma.sync GEMM, K-split 3 -> fp32 partials.
// Single-barrier pipeline: wait0 -> sync -> issue next -> compute.
// ============================================================
__global__ void __launch_bounds__(256) conv_mma_kernel()
{
    extern __shared__ u32 smu[];
    const u32 sbase = smem_u32(smu);
    const int tid = threadIdx.x;
    const int wid = tid >> 5, lane = tid & 31;
    const int g = lane >> 2, t = lane & 3;
    const int wm = wid >> 1, wn = wid & 1;
    const int bx = blockIdx.x;
    const int ks = bx / 192;
    const int rem = bx % 192;
    const int img = rem / 12;
    const int r12 = rem % 12;
    const int ot = r12 >> 1, pt = r12 & 1;
    const int obase = ot * 128, pbase = pt * 128;
    const int kbase = ks * 512;
    const u16* Asrc = g_wc3;
    const u16* Bsrc = g_xsb + ((size_t)img * 256 + pbase) * 1536;

    float acc[2][8][4];
#pragma unroll
    for (int mt = 0; mt < 2; mt++)
#pragma unroll
        for (int nt = 0; nt < 8; nt++)
#pragma unroll
            for (int q = 0; q < 4; q++) acc[mt][nt][q] = 0.0f;

    auto ldChunk = [&](int c, int buf) {
        u32 sb = sbase + buf * 40960;
        int k0 = kbase + c * 32;
#pragma unroll
        for (int it = 0; it < 6; it++) {
            int e = tid + 256 * it;
            int j = e >> 9;
            int r = (e >> 2) & 127;
            int kg = e & 3;
            cp16(sb + (j * 2560 + r * 20 + kg * 4) * 4,
                 &Asrc[(size_t)j * 1179648 + (size_t)(obase + r) * 1536 + k0 + kg * 8]);
        }
#pragma unroll
        for (int it = 0; it < 2; it++) {
            int e = tid + 256 * it;
            int r = e >> 2, kg = e & 3;
            cp16(sb + (7680 + r * 20 + kg * 4) * 4,
                 &Bsrc[(size_t)r * 1536 + k0 + kg * 8]);
        }
        CP_COMMIT();
    };

    const int aRow = wm * 32 + (lane & 15);
    const int aColw = ((lane >> 4) & 1) * 4;
    const int bRowB = wn * 64 + ((lane >> 4) & 1) * 8 + (lane & 7);
    const int bColw = ((lane >> 3) & 1) * 4;

    ldChunk(0, 0);
    for (int c = 0; c < 16; c++) {
        int buf = c & 1;
        CP_WAIT0();
        __syncthreads();
        if (c + 1 < 16) ldChunk(c + 1, buf ^ 1);
        u32 soff = sbase + buf * 40960;
#pragma unroll
        for (int k16 = 0; k16 < 2; k16++) {
            u32 bfr[8][2];
#pragma unroll
            for (int p = 0; p < 4; p++) {
                u32 addr = soff + ((7680 + (bRowB + p * 16) * 20 + k16 * 8 + bColw) << 2);
                ldm_x4(bfr[2 * p][0], bfr[2 * p][1],
                       bfr[2 * p + 1][0], bfr[2 * p + 1][1], addr);
            }
#pragma unroll
            for (int j = 0; j < 3; j++) {
#pragma unroll
                for (int mt = 0; mt < 2; mt++) {
                    u32 addr = soff + ((j * 2560 + (aRow + mt * 16) * 20 + k16 * 8 + aColw) << 2);
                    u32 a0, a1, a2, a3;
                    ldm_x4(a0, a1, a2, a3, addr);
#pragma unroll
                    for (int nt = 0; nt < 8; nt++)
                        mma16816(acc[mt][nt][0], acc[mt][nt][1],
                                 acc[mt][nt][2], acc[mt][nt][3],
                                 a0, a1, a2, a3, bfr[nt][0], bfr[nt][1]);
                }
            }
        }
    }

    float* yo = g_yp[ks];
#pragma unroll
    for (int mt = 0; mt < 2; mt++) {
        int o0 = obase + wm * 32 + mt * 16 + g;
        int o1 = o0 + 8;
#pragma unroll
        for (int nt = 0; nt < 8; nt++) {
            int p = pbase + wn * 64 + nt * 8 + 2 * t;
            *(float2*)&yo[((size_t)img * 768 + o0) * 256 + p] =
                make_float2(acc[mt][nt][0], acc[mt][nt][1]);
            *(float2*)&yo[((size_t)img * 768 + o1) * 256 + p] =
                make_float2(acc[mt][nt][2], acc[mt][nt][3]);
        }
    }
}

// ============================================================
// Kernel B2: reduce 3 K-split partials + BN1 -> g_y
// ============================================================
__global__ void __launch_bounds__(256) reduce_bn_kernel(
    const float* __restrict__ g1, const float* __restrict__ b1)
{
    int i4 = blockIdx.x * 256 + threadIdx.x;
    const float4* p0 = (const float4*)g_yp[0];
    const float4* p1 = (const float4*)g_yp[1];
    const float4* p2 = (const float4*)g_yp[2];
    float4 a = p0[i4], b = p1[i4], c = p2[i4];
    int o = (i4 >> 6) % 768;
    const float rs = rsqrtf(1.0f + EPSF);
    float bn = g1[o] * rs, bt = b1[o];
    ((float4*)g_y)[i4] = make_float4(
        (a.x + b.x + c.x) * bn + bt,
        (a.y + b.y + c.y) * bn + bt,
        (a.z + b.z + c.z) * bn + bt,
        (a.w + b.w + c.w) * bn + bt);
}

// ============================================================
// Kernel C: fused attn GEMM -> LIF2 -> out GEMM(ksplit8) -> LIF3
// (R12-measured version; xr now decoded from bf16 spikes, exact)
// smem (floats): y1s[32][256]@0 | xr[2][32][32]@8192 |
//   y2s[32][260]@10240 | ss/sp[9216]@18560  -> 111,104 B
// ============================================================
__global__ void __launch_bounds__(256, 2) attn_fused_kernel(
    const float* __restrict__ frx, const float* __restrict__ fra)
{
    extern __shared__ __align__(16) float sm[];
    float* y1s = sm;
    float* y2s = sm + 10240;
    float* ss  = sm + 18560;
    float* sp  = sm + 18560;   // overlay on ss (post-GEMM2)
    const u32 sbase = smem_u32(sm);

    const int bx = blockIdx.x;
    const int mt = bx & 31;
    const int h  = (bx >> 5) % 12;
    const int b  = bx / 384;
    const int tid = threadIdx.x;

    const int ng = tid >> 2;
    const int mg = tid & 3;
    const int n0 = ng * 4, m0 = mg * 8;
    const int kg = tid >> 5;
    const int lane = tid & 31;
    const int dg = lane >> 2;
    const int mq = lane & 3;
    const int rd = tid >> 3;
    const int rm = (tid & 7) * 4;

    const float scale1 = rsqrtf(frx[h] * 32.0f);
    const float scale2 = rsqrtf(fra[h] * 256.0f);

    float v2[4][8];
    float v3[4];
#pragma unroll
    for (int i = 0; i < 4; i++)
#pragma unroll
        for (int j = 0; j < 8; j++) v2[i][j] = 0.0f;
#pragma unroll
    for (int i = 0; i < 4; i++) v3[i] = 0.0f;

    auto issue_y1 = [&](int img) {
        const float* ybase = g_y + ((size_t)img * 768 + h * 64) * 256;
#pragma unroll
        for (int r = 0; r < 8; r++) {
            int e = tid + 256 * r;
            int d = e >> 6, c4 = (e & 63) * 4;
            cp16(sbase + (u32)(d * 256 + c4) * 4, &ybase[d * 256 + c4]);
        }
        CP_COMMIT();
    };
    auto issue_y2 = [&](int img) {
        const float* ybase = g_y + ((size_t)img * 768 + h * 64) * 256;
#pragma unroll
        for (int r = 0; r < 8; r++) {
            int e = tid + 256 * r;
            int d = e >> 6, c4 = (e & 63) * 4;
            cp16(sbase + (u32)(10240 + d * 260 + c4) * 4, &ybase[(32 + d) * 256 + c4]);
        }
        CP_COMMIT();
    };
    auto load_xr = [&](int img, int buf) {
        const u16* xbase = g_xs + ((size_t)img * 384 + h * 32) * 1024 + mt * 32;
        int d = tid >> 3, c4 = (tid & 7) * 4;
        ushort4 s4 = *(const ushort4*)&xbase[d * 1024 + c4];
        float* dst = sm + 8192 + buf * 1024;
        *(float4*)&dst[d * 32 + c4] = make_float4(
            bf16u_to_f32(s4.x) * scale1, bf16u_to_f32(s4.y) * scale1,
            bf16u_to_f32(s4.z) * scale1, bf16u_to_f32(s4.w) * scale1);
    };

    issue_y1(b);
    issue_y2(b);
    load_xr(b, 0);

    for (int t = 0; t < 4; t++) {
        const int img = t * 4 + b;
        CP_WAIT0();
        __syncthreads();
        if (t < 3) load_xr(img + 4, (t + 1) & 1);
        const float* xrs = sm + 8192 + (t & 1) * 1024;

        // GEMM1
        u64 acc[4][4];
#pragma unroll
        for (int i = 0; i < 4; i++)
#pragma unroll
            for (int q = 0; q < 4; q++) acc[i][q] = pk2(v2[i][2 * q], v2[i][2 * q + 1]);
#pragma unroll 8
        for (int d = 0; d < 32; d++) {
            float4 a4 = *(const float4*)&y1s[d * 256 + n0];
            ulonglong2 x0 = *(const ulonglong2*)&xrs[d * 32 + m0];
            ulonglong2 x1 = *(const ulonglong2*)&xrs[d * 32 + m0 + 4];
            float av[4] = {a4.x, a4.y, a4.z, a4.w};
#pragma unroll
            for (int i = 0; i < 4; i++) {
                u64 ar = pk2(av[i], av[i]);
                acc[i][0] = ffma2(ar, x0.x, acc[i][0]);
                acc[i][1] = ffma2(ar, x0.y, acc[i][1]);
                acc[i][2] = ffma2(ar, x1.x, acc[i][2]);
                acc[i][3] = ffma2(ar, x1.y, acc[i][3]);
            }
        }
        // LIF2 (spikes stored as scale2 / 0; bit-exact commuted product)
#pragma unroll
        for (int i = 0; i < 4; i++) {
            float s[8];
#pragma unroll
            for (int q = 0; q < 4; q++) {
                float lo, hi;
                upk2(acc[i][q], lo, hi);
                lo *= 0.5f; hi *= 0.5f;
                s[2 * q]     = (lo >= 1.0f) ? scale2 : 0.0f;
                s[2 * q + 1] = (hi >= 1.0f) ? scale2 : 0.0f;
                v2[i][2 * q]     = (lo >= 1.0f) ? 0.0f : lo;
                v2[i][2 * q + 1] = (hi >= 1.0f) ? 0.0f : hi;
            }
            *(float4*)&ss[(n0 + i) * 36 + m0]     = make_float4(s[0], s[1], s[2], s[3]);
            *(float4*)&ss[(n0 + i) * 36 + m0 + 4] = make_float4(s[4], s[5], s[6], s[7]);
        }
        __syncthreads();
        if (t < 3) issue_y1(img + 4);

        // GEMM2 (ksplit 8)
        u64 acc2[4][4];
#pragma unroll
        for (int i = 0; i < 4; i++)
#pragma unroll
            for (int q = 0; q < 4; q++) acc2[i][q] = 0ull;
#pragma unroll
        for (int nn = 0; nn < 32; nn += 4) {
            int n = kg * 32 + nn;
            float4 b0 = *(const float4*)&y2s[(dg +  0) * 260 + n];
            float4 b1 = *(const float4*)&y2s[(dg +  8) * 260 + n];
            float4 b2 = *(const float4*)&y2s[(dg + 16) * 260 + n];
            float4 b3 = *(const float4*)&y2s[(dg + 24) * 260 + n];
            float bv[4][4] = {{b0.x, b0.y, b0.z, b0.w}, {b1.x, b1.y, b1.z, b1.w},
                              {b2.x, b2.y, b2.z, b2.w}, {b3.x, b3.y, b3.z, b3.w}};
#pragma unroll
            for (int j = 0; j < 4; j++) {
                ulonglong2 s0 = *(const ulonglong2*)&ss[(n + j) * 36 + mq * 8];
                ulonglong2 s1 = *(const ulonglong2*)&ss[(n + j) * 36 + mq * 8 + 4];
#pragma unroll
                for (int i = 0; i < 4; i++) {
                    u64 ar = pk2(bv[i][j], bv[i][j]);
                    acc2[i][0] = ffma2(ar, s0.x, acc2[i][0]);
                    acc2[i][1] = ffma2(ar, s0.y, acc2[i][1]);
                    acc2[i][2] = ffma2(ar, s1.x, acc2[i][2]);
                    acc2[i][3] = ffma2(ar, s1.y, acc2[i][3]);
                }
            }
        }
        __syncthreads();
        if (t < 3) issue_y2(img + 4);
#pragma unroll
        for (int i = 0; i < 4; i++) {
            float* dst = &sp[kg * 1152 + (dg + 8 * i) * 36 + mq * 8];
            *(ulonglong2*)dst       = make_ulonglong2(acc2[i][0], acc2[i][1]);
            *(ulonglong2*)(dst + 4) = make_ulonglong2(acc2[i][2], acc2[i][3]);
        }
        __syncthreads();

        // reduce + LIF3 + bf16 spike store
        float4 sum = make_float4(v3[0], v3[1], v3[2], v3[3]);
#pragma unroll
        for (int k = 0; k < 8; k++) {
            float4 p = *(const float4*)&sp[k * 1152 + rd * 36 + rm];
            sum.x += p.x; sum.y += p.y; sum.z += p.z; sum.w += p.w;
        }
        sum.x *= 0.5f; sum.y *= 0.5f; sum.z *= 0.5f; sum.w *= 0.5f;
        ushort4 sb;
        sb.x = (sum.x >= 1.0f) ? 0x3F80 : 0; v3[0] = (sum.x >= 1.0f) ? 0.0f : sum.x;
        sb.y = (sum.y >= 1.0f) ? 0x3F80 : 0; v3[1] = (sum.y >= 1.0f) ? 0.0f : sum.y;
        sb.z = (sum.z >= 1.0f) ? 0x3F80 : 0; v3[2] = (sum.z >= 1.0f) ? 0.0f : sum.z;
        sb.w = (sum.w >= 1.0f) ? 0x3F80 : 0; v3[3] = (sum.w >= 1.0f) ? 0.0f : sum.w;
        *(ushort4*)&g_sp3b[((size_t)img * 384 + h * 32 + rd) * 1024 + mt * 32 + rm] = sb;
        __syncthreads();
    }
}

// ============================================================
// Kernel T: transpose bf16 spikes [c][hw] -> [hw][c] per img
// ============================================================
__global__ void __launch_bounds__(256) transpose_sp3_kernel() {
    __shared__ u16 ts[64][72];
    int bx = blockIdx.x;
    int img = bx / 96;
    int r = bx % 96;
    int c0 = (r / 16) * 64;
    int hw0 = (r % 16) * 64;
    int tid = threadIdx.x;
#pragma unroll
    for (int it = 0; it < 4; it++) {
        int e = tid + 256 * it;
        int row = e >> 4, q = e & 15;
        u64 v = *(const u64*)&g_sp3b[((size_t)img * 384 + c0 + row) * 1024 + hw0 + q * 4];
        *(u64*)&ts[row][q * 4] = v;
    }
    __syncthreads();
#pragma unroll
    for (int it = 0; it < 4; it++) {
        int e = tid + 256 * it;
        int orow = e >> 4, q = e & 15;
        u64 v = (u64)ts[q * 4 + 0][orow]
              | ((u64)ts[q * 4 + 1][orow] << 16)
              | ((u64)ts[q * 4 + 2][orow] << 32)
              | ((u64)ts[q * 4 + 3][orow] << 48);
        *(u64*)&g_sp3T[((size_t)img * 1024 + hw0 + orow) * 384 + c0 + q * 4] = v;
    }
}

// ============================================================
// Kernel D: proj as mma.sync GEMM + BN2 + residual.
// Single-barrier pipeline.
// ============================================================
__global__ void __launch_bounds__(256) proj_mma_kernel(
    const float* __restrict__ g2, const float* __restrict__ b2v,
    const float* __restrict__ x, float* __restrict__ out)
{
    extern __shared__ u32 smu[];
    const u32 sbase = smem_u32(smu);
    const int tid = threadIdx.x;
    const int wid = tid >> 5, lane = tid & 31;
    const int g = lane >> 2, t = lane & 3;
    const int wm = wid >> 1, wn = wid & 1;
    const int bx = blockIdx.x;
    const int ot = bx >> 7;
    const int nt = bx & 127;
    const int obase = ot * 128;
    const int img = nt >> 3;
    const int hw0 = (nt & 7) * 128;
    const u16* Asrc = g_wp3;
    const u16* Bsrc = g_sp3T + ((size_t)img * 1024 + hw0) * 384;

    float acc[2][8][4];
#pragma unroll
    for (int mt = 0; mt < 2; mt++)
#pragma unroll
        for (int ntt = 0; ntt < 8; ntt++)
#pragma unroll
            for (int q = 0; q < 4; q++) acc[mt][ntt][q] = 0.0f;

    auto ldChunk = [&](int c, int buf) {
        u32 sb = sbase + buf * 40960;
        int k0 = c * 32;
#pragma unroll
        for (int it = 0; it < 6; it++) {
            int e = tid + 256 * it;
            int j = e >> 9;
            int r = (e >> 2) & 127;
            int kg = e & 3;
            cp16(sb + (j * 2560 + r * 20 + kg * 4) * 4,
                 &Asrc[(size_t)j * 147456 + (size_t)(obase + r) * 384 + k0 + kg * 8]);
        }
#pragma unroll
        for (int it = 0; it < 2; it++) {
            int e = tid + 256 * it;
            int r = e >> 2, kg = e & 3;
            cp16(sb + (7680 + r * 20 + kg * 4) * 4,
                 &Bsrc[(size_t)r * 384 + k0 + kg * 8]);
        }
        CP_COMMIT();
    };

    const int aRow = wm * 32 + (lane & 15);
    const int aColw = ((lane >> 4) & 1) * 4;
    const int bRowB = wn * 64 + ((lane >> 4) & 1) * 8 + (lane & 7);
    const int bColw = ((lane >> 3) & 1) * 4;

    ldChunk(0, 0);
    for (int c = 0; c < 12; c++) {
        int buf = c & 1;
        CP_WAIT0();
        __syncthreads();
        if (c + 1 < 12) ldChunk(c + 1, buf ^ 1);
        u32 soff = sbase + buf * 40960;
#pragma unroll
        for (int k16 = 0; k16 < 2; k16++) {
            u32 bfr[8][2];
#pragma unroll
            for (int p = 0; p < 4; p++) {
                u32 addr = soff + ((7680 + (bRowB + p * 16) * 20 + k16 * 8 + bColw) << 2);
                ldm_x4(bfr[2 * p][0], bfr[2 * p][1],
                       bfr[2 * p + 1][0], bfr[2 * p + 1][1], addr);
            }
#pragma unroll
            for (int j = 0; j < 3; j++) {
#pragma unroll
                for (int mt = 0; mt < 2; mt++) {
                    u32 addr = soff + ((j * 2560 + (aRow + mt * 16) * 20 + k16 * 8 + aColw) << 2);
                    u32 a0, a1, a2, a3;
                    ldm_x4(a0, a1, a2, a3, addr);
#pragma unroll
                    for (int ntt = 0; ntt < 8; ntt++)
                        mma16816(acc[mt][ntt][0], acc[mt][ntt][1],
                                 acc[mt][ntt][2], acc[mt][ntt][3],
                                 a0, a1, a2, a3, bfr[ntt][0], bfr[ntt][1]);
                }
            }
        }
    }

    const float rs = rsqrtf(1.0f + EPSF);
#pragma unroll
    for (int mt = 0; mt < 2; mt++) {
        int o0 = obase + wm * 32 + mt * 16 + g;
        int o1 = o0 + 8;
        float bn0 = g2[o0] * rs, bt0 = b2v[o0];
        float bn1 = g2[o1] * rs, bt1 = b2v[o1];
#pragma unroll
        for (int ntt = 0; ntt < 8; ntt++) {
            int col = hw0 + wn * 64 + ntt * 8 + 2 * t;
            size_t i0 = ((size_t)img * 384 + o0) * 1024 + col;
            size_t i1 = ((size_t)img * 384 + o1) * 1024 + col;
            float2 x0 = *(const float2*)&x[i0];
            float2 x1 = *(const float2*)&x[i1];
            *(float2*)&out[i0] = make_float2(acc[mt][ntt][0] * bn0 + bt0 + x0.x,
                                             acc[mt][ntt][1] * bn0 + bt0 + x0.y);
            *(float2*)&out[i1] = make_float2(acc[mt][ntt][2] * bn1 + bt1 + x1.x,
                                             acc[mt][ntt][3] * bn1 + bt1 + x1.y);
        }
    }
}

// ============================================================
extern "C" void kernel_launch(void* const* d_in, const int* in_sizes, int n_in,
                              void* d_out, int out_size) {
    const float* x   = (const float*)d_in[0];
    const float* Wc  = (const float*)d_in[1];
    const float* g1  = (const float*)d_in[2];
    const float* b1  = (const float*)d_in[3];
    const float* Wp  = (const float*)d_in[4];
    const float* g2  = (const float*)d_in[5];
    const float* b2  = (const float*)d_in[6];
    const float* frx = (const float*)d_in[7];
    const float* fra = (const float*)d_in[8];
    float* out = (float*)d_out;

    const int smem_attn = 27776 * 4;   // 111,104 B (2 CTA/SM)
    const int smem_mma  = 81920;       // 2 x 40KB double buffer
    cudaFuncSetAttribute(attn_fused_kernel,
                         cudaFuncAttributeMaxDynamicSharedMemorySize, smem_attn);
    cudaFuncSetAttribute(conv_mma_kernel,
                         cudaFuncAttributeMaxDynamicSharedMemorySize, smem_mma);
    cudaFuncSetAttribute(proj_mma_kernel,
                         cudaFuncAttributeMaxDynamicSharedMemorySize, smem_mma);

    lif1_kernel<<<6144, 256>>>(x);
    im2col_kernel<<<6144, 256>>>();
    wsplit_kernel<<<5184, 256>>>(Wc, Wp);
    conv_mma_kernel<<<576, 256, smem_mma>>>();
    reduce_bn_kernel<<<3072, 256>>>(g1, b1);
    attn_fused_kernel<<<1536, 256, smem_attn>>>(frx, fra);
    transpose_sp3_kernel<<<1536, 256>>>();
    proj_mma_kernel<<<384, 256, smem_mma>>>(g2, b2, x, out);
}